// round 8
// baseline (speedup 1.0000x reference)
#include <cuda_runtime.h>
#include <math.h>
#include <cstdint>

#define H 768
#define SEQ 2048
#define BATCH 4
#define NTOK (BATCH * SEQ)   // 8192
#define L 9
#define M_WIN 5
#define W_WIN (2 * M_WIN + 1)  // 11
#define K2H (2 * H)            // 1536

// ---------------- scratch (__device__ globals; no allocs allowed) ----------
__device__ float g_scores[NTOK];
__device__ float g_base[NTOK * L];
__device__ float g_h[NTOK * H];          // 25 MB
__device__ float g_A[NTOK * K2H];        // 50 MB, tf32-rounded [x|ctx]
__device__ float g_B[H * K2H];           // W1^T tf32-rounded [N=768][K=1536]

// ---------------- PTX helpers ----------------------------------------------
__device__ __forceinline__ uint32_t smem_u32(const void* p) {
    uint32_t a;
    asm("{ .reg .u64 t; cvta.to.shared.u64 t, %1; cvt.u32.u64 %0, t; }" : "=r"(a) : "l"(p));
    return a;
}
__device__ __forceinline__ void cp16(uint32_t dst, const void* src) {
    asm volatile("cp.async.cg.shared.global [%0], [%1], 16;" :: "r"(dst), "l"(src));
}
__device__ __forceinline__ void cp_commit() {
    asm volatile("cp.async.commit_group;" ::: "memory");
}
template <int N>
__device__ __forceinline__ void cp_wait() {
    asm volatile("cp.async.wait_group %0;" :: "n"(N) : "memory");
}
__device__ __forceinline__ void ldsm_x4(uint32_t* r, uint32_t addr) {
    asm volatile("ldmatrix.sync.aligned.m8n8.x4.shared.b16 {%0,%1,%2,%3}, [%4];"
                 : "=r"(r[0]), "=r"(r[1]), "=r"(r[2]), "=r"(r[3]) : "r"(addr));
}
__device__ __forceinline__ void mma_tf32(float* c, const uint32_t* a, const uint32_t* b) {
    asm volatile("mma.sync.aligned.m16n8k8.row.col.f32.tf32.tf32.f32 "
                 "{%0,%1,%2,%3}, {%4,%5,%6,%7}, {%8,%9}, {%0,%1,%2,%3};"
                 : "+f"(c[0]), "+f"(c[1]), "+f"(c[2]), "+f"(c[3])
                 : "r"(a[0]), "r"(a[1]), "r"(a[2]), "r"(a[3]), "r"(b[0]), "r"(b[1]));
}
__device__ __forceinline__ float rna_tf32(float v) {
    uint32_t u;
    asm("cvt.rna.tf32.f32 %0, %1;" : "=r"(u) : "f"(v));
    return __uint_as_float(u);
}

// ============================================================
// prep: W1 [K2H][H] fp32 -> W1^T tf32-rounded fp32 [H][K2H]
// ============================================================
__global__ __launch_bounds__(256) void kprep_w(const float* __restrict__ W1)
{
    __shared__ float tile[32][33];
    int tx = threadIdx.x, ty = threadIdx.y;           // block (32,8)
    int n = blockIdx.x * 32 + tx;                     // H dim
    int k = blockIdx.y * 32 + ty;                     // K2H dim
#pragma unroll
    for (int j = 0; j < 32; j += 8)
        tile[ty + j][tx] = W1[(size_t)(k + j) * H + n];
    __syncthreads();
    int ko = blockIdx.y * 32 + tx;
    int no = blockIdx.x * 32 + ty;
#pragma unroll
    for (int j = 0; j < 32; j += 8)
        g_B[(size_t)(no + j) * K2H + ko] = rna_tf32(tile[tx][ty + j]);
}

// ============================================================
// K1: scores + base logits (R3 version — measured fastest)
// ============================================================
__global__ __launch_bounds__(256) void k1_scores_base(
    const float* __restrict__ x, const float* __restrict__ Wc,
    const float* __restrict__ bc, const float* __restrict__ wa,
    const float* __restrict__ ba)
{
    const int row = blockIdx.x;
    const int tid = threadIdx.x;
    const int lane = tid & 31, warp = tid >> 5;
    const float* xr = x + (size_t)row * H;

    float vals[10];
#pragma unroll
    for (int r = 0; r < 10; r++) vals[r] = 0.f;

    for (int h = tid; h < H; h += 256) {
        float xv = xr[h];
        vals[0] += xv * wa[h];
        const float* wcr = Wc + h * L;
#pragma unroll
        for (int l = 0; l < L; l++) vals[1 + l] += xv * wcr[l];
    }
    __shared__ float red[8][10];
#pragma unroll
    for (int r = 0; r < 10; r++) {
        float v = vals[r];
#pragma unroll
        for (int o = 16; o > 0; o >>= 1) v += __shfl_down_sync(0xffffffffu, v, o);
        if (lane == 0) red[warp][r] = v;
    }
    __syncthreads();
    if (tid < 10) {
        float t = 0.f;
#pragma unroll
        for (int w = 0; w < 8; w++) t += red[w][tid];
        if (tid == 0) g_scores[row] = t + ba[0];
        else g_base[row * L + (tid - 1)] = t + bc[tid - 1];
    }
}

// ============================================================
// K2: window softmax + weighted context; emit [x|ctx] tf32 fp32
// ============================================================
__global__ __launch_bounds__(256) void k2_ctx(const float* __restrict__ x)
{
    const int row = blockIdx.x;
    const int b = row / SEQ;
    const int s = row % SEQ;
    const int tid = threadIdx.x;

    __shared__ float attn_s[W_WIN];
    if (tid < 32) {
        int w = tid;
        int idx = s + (w - M_WIN);
        bool valid = (w < W_WIN) && (idx >= 0) && (idx < SEQ);
        float sc = valid ? g_scores[b * SEQ + idx] : -INFINITY;
        float m = sc;
#pragma unroll
        for (int o = 16; o > 0; o >>= 1) m = fmaxf(m, __shfl_xor_sync(0xffffffffu, m, o));
        float e = valid ? expf(sc - m) : 0.f;
        float sum = e;
#pragma unroll
        for (int o = 16; o > 0; o >>= 1) sum += __shfl_xor_sync(0xffffffffu, sum, o);
        if (w < W_WIN) attn_s[w] = e / sum;
    }
    __syncthreads();

    float a[W_WIN];
    const float* rows[W_WIN];
#pragma unroll
    for (int w = 0; w < W_WIN; w++) {
        a[w] = attn_s[w];
        int idx = s + (w - M_WIN);
        idx = max(0, min(SEQ - 1, idx));
        rows[w] = x + ((size_t)(b * SEQ + idx)) * H;
    }

    float* arow = g_A + (size_t)row * K2H;
    for (int h = tid; h < H; h += 256) {
        float acc = 0.f;
#pragma unroll
        for (int w = 0; w < W_WIN; w++) acc += a[w] * rows[w][h];
        arow[h] = rna_tf32(rows[M_WIN][h]);
        arow[H + h] = rna_tf32(acc);
    }
}

// ============================================================
// K3: TF32 HMMA GEMM: g_h = [x|ctx] @ W1 + b1
// BM=128 BN=128 BK=64(floats), 3-stage cp.async single-sync pipeline,
// SW128 smem (256B logical rows = 2 x 128B), 512 thr (16 warps 4Mx4N)
// ============================================================
#define BM3 128
#define BN3 128
#define BK3 64
#define NIT (K2H / BK3)            // 24
#define NSTG 3
#define SA 0
#define SB (32 * 1024)
#define STAGE_BYTES (64 * 1024)
#define SMEM_TOTAL3 (1024 + NSTG * STAGE_BYTES)

// chunk -> smem byte offset. row = m/n index, ch = 16B-chunk index (0..15)
__device__ __forceinline__ uint32_t k3_off(int row, int ch) {
    int rowIdx = row * 2 + (ch >> 3);
    return rowIdx * 128 + (((ch & 7) ^ (rowIdx & 7)) << 4);
}

__global__ __launch_bounds__(512, 1) void k3_mma(const float* __restrict__ b1)
{
    extern __shared__ char smem_raw[];
    uint32_t sraw = smem_u32(smem_raw);
    const uint32_t sbase = (sraw + 1023u) & ~1023u;

    const int tid = threadIdx.x;
    const int lane = tid & 31, wid = tid >> 5;
    const int warpM = wid & 3;        // 4 M warps
    const int warpN = wid >> 2;       // 4 N warps
    const int m0 = blockIdx.y * BM3;
    const int n0 = blockIdx.x * BN3;

    // ---- gmem load roles: thread t -> row t>>2, chunks (t&3)*4 .. +3 ----
    const int ldRow = tid >> 2;
    const int ldC0 = (tid & 3) * 4;
    const float* gA = g_A + (size_t)(m0 + ldRow) * K2H + ldC0 * 4;
    const float* gB = g_B + (size_t)(n0 + ldRow) * K2H + ldC0 * 4;
    uint32_t dOff[4];
#pragma unroll
    for (int i = 0; i < 4; i++) dOff[i] = k3_off(ldRow, ldC0 + i);

    // ---- ldmatrix address prep (same algebra as bf16 version) ----
    int aRow[2];
    aRow[0] = warpM * 32 + (lane & 15);
    aRow[1] = aRow[0] + 16;
    const int aCB = lane >> 4;
    int bRow[2];
#pragma unroll
    for (int p = 0; p < 2; p++)
        bRow[p] = warpN * 32 + p * 16 + (lane & 7) + ((lane >> 4) << 3);
    const int bCB = (lane >> 3) & 1;

    float c[2][4][4];
#pragma unroll
    for (int f = 0; f < 2; f++)
#pragma unroll
        for (int j = 0; j < 4; j++)
#pragma unroll
            for (int q = 0; q < 4; q++) c[f][j][q] = 0.f;

    // ---- prologue: stages 0..NSTG-2 ----
#pragma unroll
    for (int st = 0; st < NSTG - 1; st++) {
        uint32_t sd = sbase + st * STAGE_BYTES;
        const int kb = st * BK3;
#pragma unroll
        for (int i = 0; i < 4; i++) {
            cp16(sd + SA + dOff[i], gA + kb + i * 4);
            cp16(sd + SB + dOff[i], gB + kb + i * 4);
        }
        cp_commit();
    }

    for (int it = 0; it < NIT; ++it) {
        cp_wait<NSTG - 2>();      // stage `it` resident
        __syncthreads();          // all warps done reading stage it-1

        const int pf = it + NSTG - 1;
        if (pf < NIT) {
            const uint32_t sn = sbase + (pf % NSTG) * STAGE_BYTES;
            const int kb = pf * BK3;
#pragma unroll
            for (int i = 0; i < 4; i++) {
                cp16(sn + SA + dOff[i], gA + kb + i * 4);
                cp16(sn + SB + dOff[i], gB + kb + i * 4);
            }
        }
        cp_commit();

        const uint32_t sd = sbase + (it % NSTG) * STAGE_BYTES;
#pragma unroll
        for (int s = 0; s < 8; s++) {          // 8 k8-steps per BK=64
            uint32_t af[2][4], bf[2][4];
#pragma unroll
            for (int f = 0; f < 2; f++)
                ldsm_x4(af[f], sd + SA + k3_off(aRow[f], 2 * s + aCB));
#pragma unroll
            for (int p = 0; p < 2; p++)
                ldsm_x4(bf[p], sd + SB + k3_off(bRow[p], 2 * s + bCB));
#pragma unroll
            for (int p = 0; p < 2; p++)
#pragma unroll
                for (int f = 0; f < 2; f++) {
                    mma_tf32(c[f][2 * p],     af[f], bf[p]);
                    mma_tf32(c[f][2 * p + 1], af[f], bf[p] + 2);
                }
        }
    }

    // ---- epilogue: +b1 -> g_h ----
    const int mBase = m0 + warpM * 32 + (lane >> 2);
    const int nBase = n0 + warpN * 32 + (lane & 3) * 2;
#pragma unroll
    for (int f = 0; f < 2; f++) {
#pragma unroll
        for (int j = 0; j < 4; j++) {
            int n = nBase + j * 8;
            float b0 = b1[n], b1v = b1[n + 1];
            int m = mBase + f * 16;
            float2 o0 = make_float2(c[f][j][0] + b0, c[f][j][1] + b1v);
            float2 o1 = make_float2(c[f][j][2] + b0, c[f][j][3] + b1v);
            *(float2*)&g_h[(size_t)m * H + n] = o0;
            *(float2*)&g_h[(size_t)(m + 8) * H + n] = o1;
        }
    }
}

// ============================================================
// K4: layernorm + exact gelu + W2 + combine
// 768 threads, 4 rows concurrently (192 thr/row, float4 loads), 16 rows/blk
// ============================================================
#define K4_ROWS 16
__global__ __launch_bounds__(768) void k4_ln_gelu_out(
    const float* __restrict__ gamma, const float* __restrict__ beta,
    const float* __restrict__ W2, const float* __restrict__ b2,
    float* __restrict__ out)
{
    const int tid = threadIdx.x;
    const int lane = tid & 31;
    const int rgrp = tid / 192;       // 0..3 concurrent rows
    const int tIn = tid % 192;        // thread within row
    const int warpIn = tIn >> 5;      // 0..5

    __shared__ float w2s[H * L];      // 27 KB
    __shared__ float gb[2 * H];       // 6 KB
    for (int i = tid; i < H * L; i += 768) w2s[i] = W2[i];
    for (int i = tid; i < H; i += 768) { gb[i] = gamma[i]; gb[H + i] = beta[i]; }

    __shared__ float rbuf[4][6][2];
    __shared__ float red[4][6][L];
    __shared__ float musd[4][2];
    __syncthreads();

#pragma unroll
    for (int pass = 0; pass < K4_ROWS / 4; pass++) {
        const int row = blockIdx.x * K4_ROWS + pass * 4 + rgrp;
        const float4 hv = ((const float4*)(g_h + (size_t)row * H))[tIn];

        float s1 = hv.x + hv.y + hv.z + hv.w;
        float s2 = hv.x * hv.x + hv.y * hv.y + hv.z * hv.z + hv.w * hv.w;
#pragma unroll
        for (int o = 16; o > 0; o >>= 1) {
            s1 += __shfl_down_sync(0xffffffffu, s1, o);
            s2 += __shfl_down_sync(0xffffffffu, s2, o);
        }
        if (lane == 0) { rbuf[rgrp][warpIn][0] = s1; rbuf[rgrp][warpIn][1] = s2; }
        __syncthreads();
        if (tIn == 0) {
            float a = 0.f, bsum = 0.f;
#pragma unroll
            for (int w = 0; w < 6; w++) { a += rbuf[rgrp][w][0]; bsum += rbuf[rgrp][w][1]; }
            float mu = a * (1.0f / H);
            float var = bsum * (1.0f / H) - mu * mu;
            musd[rgrp][0] = mu;
            musd[rgrp][1] = rsqrtf(var + 1e-5f);
        }
        __syncthreads();
        const float mu = musd[rgrp][0];
        const float rstd = musd[rgrp][1];

        float bl[L];
#pragma unroll
        for (int l = 0; l < L; l++) bl[l] = 0.f;
        float he[4] = {hv.x, hv.y, hv.z, hv.w};
#pragma unroll
        for (int e = 0; e < 4; e++) {
            int idx = tIn * 4 + e;
            float xv = (he[e] - mu) * rstd * gb[idx] + gb[H + idx];
            float g = xv * normcdff(xv);
            const float* w2r = &w2s[idx * L];
#pragma unroll
            for (int l = 0; l < L; l++) bl[l] += g * w2r[l];
        }
#pragma unroll
        for (int r = 0; r < L; r++) {
            float val = bl[r];
#pragma unroll
            for (int o = 16; o > 0; o >>= 1) val += __shfl_down_sync(0xffffffffu, val, o);
            if (lane == 0) red[rgrp][warpIn][r] = val;
        }
        __syncthreads();
        if (tIn < L) {
            float t = 0.f;
#pragma unroll
            for (int w = 0; w < 6; w++) t += red[rgrp][w][tIn];
            out[row * L + tIn] = 0.5f * g_base[row * L + tIn] + 0.5f * (t + b2[tIn]);
        }
        __syncthreads();
    }
}

// ============================================================
extern "C" void kernel_launch(void* const* d_in, const int* in_sizes, int n_in,
                              void* d_out, int out_size)
{
    const float* x     = (const float*)d_in[0];
    const float* Wc    = (const float*)d_in[1];
    const float* bc    = (const float*)d_in[2];
    const float* wa    = (const float*)d_in[3];
    const float* ba    = (const float*)d_in[4];
    const float* W1    = (const float*)d_in[5];
    const float* b1    = (const float*)d_in[6];
    const float* gamma = (const float*)d_in[7];
    const float* beta  = (const float*)d_in[8];
    const float* W2    = (const float*)d_in[9];
    const float* b2    = (const float*)d_in[10];
    float* out = (float*)d_out;

    cudaFuncSetAttribute(k3_mma, cudaFuncAttributeMaxDynamicSharedMemorySize, SMEM_TOTAL3);

    kprep_w<<<dim3(H / 32, K2H / 32), dim3(32, 8)>>>(W1);
    k1_scores_base<<<NTOK, 256>>>(x, Wc, bc, wa, ba);
    k2_ctx<<<NTOK, 256>>>(x);
    k3_mma<<<dim3(H / BN3, NTOK / BM3), 512, SMEM_TOTAL3>>>(b1);
    k4_ln_gelu_out<<<NTOK / K4_ROWS, 768>>>(gamma, beta, W2, b2, out);
}

// round 9
// speedup vs baseline: 1.0703x; 1.0703x over previous
#include <cuda_runtime.h>
#include <cuda_bf16.h>
#include <math.h>
#include <cstdint>

#define H 768
#define SEQ 2048
#define BATCH 4
#define NTOK (BATCH * SEQ)   // 8192
#define L 9
#define M_WIN 5
#define W_WIN (2 * M_WIN + 1)  // 11
#define K2H (2 * H)            // 1536

// ---------------- scratch (__device__ globals; no allocs allowed) ----------
__device__ float g_scores[NTOK];
__device__ float g_base[NTOK * L];
__device__ float g_h[NTOK * H];                       // 25 MB
__device__ __nv_bfloat16 g_Ahi[NTOK * K2H];           // 25 MB
__device__ __nv_bfloat16 g_Alo[NTOK * K2H];           // 25 MB
__device__ __nv_bfloat16 g_Bhi[H * K2H];              // W1^T hi  [N=768][K=1536]
__device__ __nv_bfloat16 g_Blo[H * K2H];              // W1^T lo

// ---------------- PTX helpers ----------------------------------------------
__device__ __forceinline__ uint32_t smem_u32(const void* p) {
    uint32_t a;
    asm("{ .reg .u64 t; cvta.to.shared.u64 t, %1; cvt.u32.u64 %0, t; }" : "=r"(a) : "l"(p));
    return a;
}
__device__ __forceinline__ void cp16(uint32_t dst, const void* src) {
    asm volatile("cp.async.cg.shared.global [%0], [%1], 16;" :: "r"(dst), "l"(src));
}
__device__ __forceinline__ void cp_commit() {
    asm volatile("cp.async.commit_group;" ::: "memory");
}
template <int N>
__device__ __forceinline__ void cp_wait() {
    asm volatile("cp.async.wait_group %0;" :: "n"(N) : "memory");
}
__device__ __forceinline__ void ldsm_x4(uint32_t* r, uint32_t addr) {
    asm volatile("ldmatrix.sync.aligned.m8n8.x4.shared.b16 {%0,%1,%2,%3}, [%4];"
                 : "=r"(r[0]), "=r"(r[1]), "=r"(r[2]), "=r"(r[3]) : "r"(addr));
}
__device__ __forceinline__ void mma_bf16(float* c, const uint32_t* a, const uint32_t* b) {
    asm volatile("mma.sync.aligned.m16n8k16.row.col.f32.bf16.bf16.f32 "
                 "{%0,%1,%2,%3}, {%4,%5,%6,%7}, {%8,%9}, {%0,%1,%2,%3};"
                 : "+f"(c[0]), "+f"(c[1]), "+f"(c[2]), "+f"(c[3])
                 : "r"(a[0]), "r"(a[1]), "r"(a[2]), "r"(a[3]), "r"(b[0]), "r"(b[1]));
}

// ============================================================
// prep: W1 [K2H][H] fp32 -> W1^T bf16 hi/lo [H][K2H]
// ============================================================
__global__ __launch_bounds__(256) void kprep_w(const float* __restrict__ W1)
{
    __shared__ float tile[32][33];
    int tx = threadIdx.x, ty = threadIdx.y;           // block (32,8)
    int n = blockIdx.x * 32 + tx;                     // H dim
    int k = blockIdx.y * 32 + ty;                     // K2H dim
#pragma unroll
    for (int j = 0; j < 32; j += 8)
        tile[ty + j][tx] = W1[(size_t)(k + j) * H + n];
    __syncthreads();
    int ko = blockIdx.y * 32 + tx;                    // now contiguous K
    int no = blockIdx.x * 32 + ty;
#pragma unroll
    for (int j = 0; j < 32; j += 8) {
        float v = tile[tx][ty + j];
        __nv_bfloat16 hi = __float2bfloat16(v);
        size_t o = (size_t)(no + j) * K2H + ko;
        g_Bhi[o] = hi;
        g_Blo[o] = __float2bfloat16(v - __bfloat162float(hi));
    }
}

// ============================================================
// K1: scores + base logits
// ============================================================
__global__ __launch_bounds__(256) void k1_scores_base(
    const float* __restrict__ x, const float* __restrict__ Wc,
    const float* __restrict__ bc, const float* __restrict__ wa,
    const float* __restrict__ ba)
{
    const int row = blockIdx.x;
    const int tid = threadIdx.x;
    const int lane = tid & 31, warp = tid >> 5;
    const float* xr = x + (size_t)row * H;

    float vals[10];
#pragma unroll
    for (int r = 0; r < 10; r++) vals[r] = 0.f;

    for (int h = tid; h < H; h += 256) {
        float xv = xr[h];
        vals[0] += xv * wa[h];
        const float* wcr = Wc + h * L;
#pragma unroll
        for (int l = 0; l < L; l++) vals[1 + l] += xv * wcr[l];
    }
    __shared__ float red[8][10];
#pragma unroll
    for (int r = 0; r < 10; r++) {
        float v = vals[r];
#pragma unroll
        for (int o = 16; o > 0; o >>= 1) v += __shfl_down_sync(0xffffffffu, v, o);
        if (lane == 0) red[warp][r] = v;
    }
    __syncthreads();
    if (tid < 10) {
        float t = 0.f;
#pragma unroll
        for (int w = 0; w < 8; w++) t += red[w][tid];
        if (tid == 0) g_scores[row] = t + ba[0];
        else g_base[row * L + (tid - 1)] = t + bc[tid - 1];
    }
}

// ============================================================
// K2: window softmax + weighted context; emit [x|ctx] bf16 hi/lo
// ============================================================
__global__ __launch_bounds__(256) void k2_ctx(const float* __restrict__ x)
{
    const int row = blockIdx.x;
    const int b = row / SEQ;
    const int s = row % SEQ;
    const int tid = threadIdx.x;

    __shared__ float attn_s[W_WIN];
    if (tid < 32) {
        int w = tid;
        int idx = s + (w - M_WIN);
        bool valid = (w < W_WIN) && (idx >= 0) && (idx < SEQ);
        float sc = valid ? g_scores[b * SEQ + idx] : -INFINITY;
        float m = sc;
#pragma unroll
        for (int o = 16; o > 0; o >>= 1) m = fmaxf(m, __shfl_xor_sync(0xffffffffu, m, o));
        float e = valid ? expf(sc - m) : 0.f;
        float sum = e;
#pragma unroll
        for (int o = 16; o > 0; o >>= 1) sum += __shfl_xor_sync(0xffffffffu, sum, o);
        if (w < W_WIN) attn_s[w] = e / sum;
    }
    __syncthreads();

    float a[W_WIN];
    const float* rows[W_WIN];
#pragma unroll
    for (int w = 0; w < W_WIN; w++) {
        a[w] = attn_s[w];
        int idx = s + (w - M_WIN);
        idx = max(0, min(SEQ - 1, idx));
        rows[w] = x + ((size_t)(b * SEQ + idx)) * H;
    }

    __nv_bfloat16* ahi = g_Ahi + (size_t)row * K2H;
    __nv_bfloat16* alo = g_Alo + (size_t)row * K2H;
    for (int h = tid; h < H; h += 256) {
        float acc = 0.f;
#pragma unroll
        for (int w = 0; w < W_WIN; w++) acc += a[w] * rows[w][h];
        float xc = rows[M_WIN][h];
        __nv_bfloat16 h1 = __float2bfloat16(xc);
        ahi[h] = h1;
        alo[h] = __float2bfloat16(xc - __bfloat162float(h1));
        __nv_bfloat16 h2 = __float2bfloat16(acc);
        ahi[H + h] = h2;
        alo[H + h] = __float2bfloat16(acc - __bfloat162float(h2));
    }
}

// ============================================================
// K3: HMMA (mma.sync bf16, 3-split) GEMM: g_h = [x|ctx] @ W1 + b1
// BM=128 BN=128 BK=64, 3-stage cp.async single-sync pipeline,
// SW128 smem, 512 thr (16 warps: 4M x 4N, warp tile 32x32)
// term-major MMA ordering: 8 independent MMAs between acc reuse
// ============================================================
#define BM3 128
#define BN3 128
#define BK3 64
#define NIT (K2H / BK3)            // 24
#define NSTG 3
#define SA_HI 0
#define SA_LO (16 * 1024)
#define SB_HI (32 * 1024)
#define SB_LO (48 * 1024)
#define STAGE_BYTES (64 * 1024)
#define SMEM_TOTAL3 (1024 + NSTG * STAGE_BYTES)

__global__ __launch_bounds__(512, 1) void k3_mma(const float* __restrict__ b1)
{
    extern __shared__ char smem_raw[];
    uint32_t sraw = smem_u32(smem_raw);
    const uint32_t sbase = (sraw + 1023u) & ~1023u;

    const int tid = threadIdx.x;
    const int lane = tid & 31, wid = tid >> 5;
    const int warpM = wid & 3;        // 4 M warps
    const int warpN = wid >> 2;       // 4 N warps
    const int m0 = blockIdx.y * BM3;
    const int n0 = blockIdx.x * BN3;

    // ---- gmem load roles: thread t -> row t>>2, chunks (t&3)*2 .. +1 ----
    const int ldRow = tid >> 2;
    const int ldC0 = (tid & 3) * 2;
    const __nv_bfloat16* gAh = g_Ahi + (size_t)(m0 + ldRow) * K2H + ldC0 * 8;
    const __nv_bfloat16* gAl = g_Alo + (size_t)(m0 + ldRow) * K2H + ldC0 * 8;
    const __nv_bfloat16* gBh = g_Bhi + (size_t)(n0 + ldRow) * K2H + ldC0 * 8;
    const __nv_bfloat16* gBl = g_Blo + (size_t)(n0 + ldRow) * K2H + ldC0 * 8;
    uint32_t dOff[2];
#pragma unroll
    for (int i = 0; i < 2; i++) {
        int c = ldC0 + i;
        dOff[i] = ldRow * 128 + ((c ^ (ldRow & 7)) << 4);
    }

    // ---- ldmatrix address prep ----
    int aRow[2], aX[2];
    aRow[0] = warpM * 32 + (lane & 15);
    aRow[1] = aRow[0] + 16;
    aX[0] = aRow[0] & 7;
    aX[1] = aRow[1] & 7;
    const int aCB = lane >> 4;
    int bRow[2], bX[2];
#pragma unroll
    for (int p = 0; p < 2; p++) {
        bRow[p] = warpN * 32 + p * 16 + (lane & 7) + ((lane >> 4) << 3);
        bX[p] = bRow[p] & 7;
    }
    const int bCB = (lane >> 3) & 1;

    float c[2][4][4];
#pragma unroll
    for (int f = 0; f < 2; f++)
#pragma unroll
        for (int j = 0; j < 4; j++)
#pragma unroll
            for (int q = 0; q < 4; q++) c[f][j][q] = 0.f;

    // ---- prologue: stages 0..NSTG-2 ----
#pragma unroll
    for (int st = 0; st < NSTG - 1; st++) {
        uint32_t sd = sbase + st * STAGE_BYTES;
        const int kb = st * BK3;
#pragma unroll
        for (int i = 0; i < 2; i++) {
            cp16(sd + SA_HI + dOff[i], gAh + kb + i * 8);
            cp16(sd + SA_LO + dOff[i], gAl + kb + i * 8);
            cp16(sd + SB_HI + dOff[i], gBh + kb + i * 8);
            cp16(sd + SB_LO + dOff[i], gBl + kb + i * 8);
        }
        cp_commit();
    }

    for (int it = 0; it < NIT; ++it) {
        cp_wait<NSTG - 2>();      // stage `it` resident
        __syncthreads();          // all warps done reading stage it-1

        const int pf = it + NSTG - 1;
        if (pf < NIT) {
            const uint32_t sn = sbase + (pf % NSTG) * STAGE_BYTES;
            const int kb = pf * BK3;
#pragma unroll
            for (int i = 0; i < 2; i++) {
                cp16(sn + SA_HI + dOff[i], gAh + kb + i * 8);
                cp16(sn + SA_LO + dOff[i], gAl + kb + i * 8);
                cp16(sn + SB_HI + dOff[i], gBh + kb + i * 8);
                cp16(sn + SB_LO + dOff[i], gBl + kb + i * 8);
            }
        }
        cp_commit();

        const uint32_t sd = sbase + (it % NSTG) * STAGE_BYTES;
#pragma unroll
        for (int s = 0; s < 4; s++) {
            uint32_t ah[2][4], al[2][4], bh[2][4], bl[2][4];
#pragma unroll
            for (int f = 0; f < 2; f++) {
                uint32_t off = aRow[f] * 128 + (((2 * s + aCB) ^ aX[f]) << 4);
                ldsm_x4(ah[f], sd + SA_HI + off);
                ldsm_x4(al[f], sd + SA_LO + off);
            }
#pragma unroll
            for (int p = 0; p < 2; p++) {
                uint32_t off = bRow[p] * 128 + (((2 * s + bCB) ^ bX[p]) << 4);
                ldsm_x4(bh[p], sd + SB_HI + off);
                ldsm_x4(bl[p], sd + SB_LO + off);
            }
            // term 1: Ahi*Bhi — 8 independent MMAs
#pragma unroll
            for (int p = 0; p < 2; p++)
#pragma unroll
                for (int f = 0; f < 2; f++) {
                    mma_bf16(c[f][2 * p],     ah[f], bh[p]);
                    mma_bf16(c[f][2 * p + 1], ah[f], bh[p] + 2);
                }
            // term 2: Ahi*Blo — 8 independent MMAs
#pragma unroll
            for (int p = 0; p < 2; p++)
#pragma unroll
                for (int f = 0; f < 2; f++) {
                    mma_bf16(c[f][2 * p],     ah[f], bl[p]);
                    mma_bf16(c[f][2 * p + 1], ah[f], bl[p] + 2);
                }
            // term 3: Alo*Bhi — 8 independent MMAs
#pragma unroll
            for (int p = 0; p < 2; p++)
#pragma unroll
                for (int f = 0; f < 2; f++) {
                    mma_bf16(c[f][2 * p],     al[f], bh[p]);
                    mma_bf16(c[f][2 * p + 1], al[f], bh[p] + 2);
                }
        }
    }

    // ---- epilogue: +b1 -> g_h ----
    const int mBase = m0 + warpM * 32 + (lane >> 2);
    const int nBase = n0 + warpN * 32 + (lane & 3) * 2;
#pragma unroll
    for (int f = 0; f < 2; f++) {
#pragma unroll
        for (int j = 0; j < 4; j++) {
            int n = nBase + j * 8;
            float b0 = b1[n], b1v = b1[n + 1];
            int m = mBase + f * 16;
            float2 o0 = make_float2(c[f][j][0] + b0, c[f][j][1] + b1v);
            float2 o1 = make_float2(c[f][j][2] + b0, c[f][j][3] + b1v);
            *(float2*)&g_h[(size_t)m * H + n] = o0;
            *(float2*)&g_h[(size_t)(m + 8) * H + n] = o1;
        }
    }
}

// ============================================================
// K4: layernorm + exact gelu + W2 + combine
// 768 threads, 4 rows concurrently (192 thr/row, float4 loads), 16 rows/blk
// ============================================================
#define K4_ROWS 16
__global__ __launch_bounds__(768) void k4_ln_gelu_out(
    const float* __restrict__ gamma, const float* __restrict__ beta,
    const float* __restrict__ W2, const float* __restrict__ b2,
    float* __restrict__ out)
{
    const int tid = threadIdx.x;
    const int lane = tid & 31;
    const int rgrp = tid / 192;       // 0..3 concurrent rows
    const int tIn = tid % 192;        // thread within row
    const int warpIn = tIn >> 5;      // 0..5

    __shared__ float w2s[H * L];      // 27 KB
    __shared__ float gb[2 * H];       // 6 KB
    for (int i = tid; i < H * L; i += 768) w2s[i] = W2[i];
    for (int i = tid; i < H; i += 768) { gb[i] = gamma[i]; gb[H + i] = beta[i]; }

    __shared__ float rbuf[4][6][2];
    __shared__ float red[4][6][L];
    __shared__ float musd[4][2];
    __syncthreads();

#pragma unroll
    for (int pass = 0; pass < K4_ROWS / 4; pass++) {
        const int row = blockIdx.x * K4_ROWS + pass * 4 + rgrp;
        const float4 hv = ((const float4*)(g_h + (size_t)row * H))[tIn];

        float s1 = hv.x + hv.y + hv.z + hv.w;
        float s2 = hv.x * hv.x + hv.y * hv.y + hv.z * hv.z + hv.w * hv.w;
#pragma unroll
        for (int o = 16; o > 0; o >>= 1) {
            s1 += __shfl_down_sync(0xffffffffu, s1, o);
            s2 += __shfl_down_sync(0xffffffffu, s2, o);
        }
        if (lane == 0) { rbuf[rgrp][warpIn][0] = s1; rbuf[rgrp][warpIn][1] = s2; }
        __syncthreads();
        if (tIn == 0) {
            float a = 0.f, bsum = 0.f;
#pragma unroll
            for (int w = 0; w < 6; w++) { a += rbuf[rgrp][w][0]; bsum += rbuf[rgrp][w][1]; }
            float mu = a * (1.0f / H);
            float var = bsum * (1.0f / H) - mu * mu;
            musd[rgrp][0] = mu;
            musd[rgrp][1] = rsqrtf(var + 1e-5f);
        }
        __syncthreads();
        const float mu = musd[rgrp][0];
        const float rstd = musd[rgrp][1];

        float bl[L];
#pragma unroll
        for (int l = 0; l < L; l++) bl[l] = 0.f;
        float he[4] = {hv.x, hv.y, hv.z, hv.w};
#pragma unroll
        for (int e = 0; e < 4; e++) {
            int idx = tIn * 4 + e;
            float xv = (he[e] - mu) * rstd * gb[idx] + gb[H + idx];
            float g = xv * normcdff(xv);
            const float* w2r = &w2s[idx * L];
#pragma unroll
            for (int l = 0; l < L; l++) bl[l] += g * w2r[l];
        }
#pragma unroll
        for (int r = 0; r < L; r++) {
            float val = bl[r];
#pragma unroll
            for (int o = 16; o > 0; o >>= 1) val += __shfl_down_sync(0xffffffffu, val, o);
            if (lane == 0) red[rgrp][warpIn][r] = val;
        }
        __syncthreads();
        if (tIn < L) {
            float t = 0.f;
#pragma unroll
            for (int w = 0; w < 6; w++) t += red[rgrp][w][tIn];
            out[row * L + tIn] = 0.5f * g_base[row * L + tIn] + 0.5f * (t + b2[tIn]);
        }
        __syncthreads();
    }
}

// ============================================================
extern "C" void kernel_launch(void* const* d_in, const int* in_sizes, int n_in,
                              void* d_out, int out_size)
{
    const float* x     = (const float*)d_in[0];
    const float* Wc    = (const float*)d_in[1];
    const float* bc    = (const float*)d_in[2];
    const float* wa    = (const float*)d_in[3];
    const float* ba    = (const float*)d_in[4];
    const float* W1    = (const float*)d_in[5];
    const float* b1    = (const float*)d_in[6];
    const float* gamma = (const float*)d_in[7];
    const float* beta  = (const float*)d_in[8];
    const float* W2    = (const float*)d_in[9];
    const float* b2    = (const float*)d_in[10];
    float* out = (float*)d_out;

    cudaFuncSetAttribute(k3_mma, cudaFuncAttributeMaxDynamicSharedMemorySize, SMEM_TOTAL3);

    kprep_w<<<dim3(H / 32, K2H / 32), dim3(32, 8)>>>(W1);
    k1_scores_base<<<NTOK, 256>>>(x, Wc, bc, wa, ba);
    k2_ctx<<<NTOK, 256>>>(x);
    k3_mma<<<dim3(H / BN3, NTOK / BM3), 512, SMEM_TOTAL3>>>(b1);
    k4_ln_gelu_out<<<NTOK / K4_ROWS, 768>>>(gamma, beta, W2, b2, out);
}

// round 10
// speedup vs baseline: 1.3753x; 1.2850x over previous
#include <cuda_runtime.h>
#include <cuda_fp16.h>
#include <math.h>
#include <cstdint>

#define H 768
#define SEQ 2048
#define BATCH 4
#define NTOK (BATCH * SEQ)   // 8192
#define L 9
#define M_WIN 5
#define W_WIN (2 * M_WIN + 1)  // 11
#define K2H (2 * H)            // 1536

// ---------------- scratch (__device__ globals; no allocs allowed) ----------
__device__ float g_scores[NTOK];
__device__ float g_base[NTOK * L];
__device__ float g_h[NTOK * H];          // 25 MB
__device__ __half g_A[NTOK * K2H];       // 25 MB, fp16 [x|ctx]
__device__ __half g_B[H * K2H];          // W1^T fp16 [N=768][K=1536]

// ---------------- PTX helpers ----------------------------------------------
__device__ __forceinline__ uint32_t smem_u32(const void* p) {
    uint32_t a;
    asm("{ .reg .u64 t; cvta.to.shared.u64 t, %1; cvt.u32.u64 %0, t; }" : "=r"(a) : "l"(p));
    return a;
}
__device__ __forceinline__ void cp16(uint32_t dst, const void* src) {
    asm volatile("cp.async.cg.shared.global [%0], [%1], 16;" :: "r"(dst), "l"(src));
}
__device__ __forceinline__ void cp_commit() {
    asm volatile("cp.async.commit_group;" ::: "memory");
}
template <int N>
__device__ __forceinline__ void cp_wait() {
    asm volatile("cp.async.wait_group %0;" :: "n"(N) : "memory");
}
__device__ __forceinline__ void ldsm_x4(uint32_t* r, uint32_t addr) {
    asm volatile("ldmatrix.sync.aligned.m8n8.x4.shared.b16 {%0,%1,%2,%3}, [%4];"
                 : "=r"(r[0]), "=r"(r[1]), "=r"(r[2]), "=r"(r[3]) : "r"(addr));
}
__device__ __forceinline__ void mma_f16(float* c, const uint32_t* a, const uint32_t* b) {
    asm volatile("mma.sync.aligned.m16n8k16.row.col.f32.f16.f16.f32 "
                 "{%0,%1,%2,%3}, {%4,%5,%6,%7}, {%8,%9}, {%0,%1,%2,%3};"
                 : "+f"(c[0]), "+f"(c[1]), "+f"(c[2]), "+f"(c[3])
                 : "r"(a[0]), "r"(a[1]), "r"(a[2]), "r"(a[3]), "r"(b[0]), "r"(b[1]));
}

// ============================================================
// prep: W1 [K2H][H] fp32 -> W1^T fp16 [H][K2H]
// ============================================================
__global__ __launch_bounds__(256) void kprep_w(const float* __restrict__ W1)
{
    __shared__ float tile[32][33];
    int tx = threadIdx.x, ty = threadIdx.y;           // block (32,8)
    int n = blockIdx.x * 32 + tx;                     // H dim
    int k = blockIdx.y * 32 + ty;                     // K2H dim
#pragma unroll
    for (int j = 0; j < 32; j += 8)
        tile[ty + j][tx] = W1[(size_t)(k + j) * H + n];
    __syncthreads();
    int ko = blockIdx.y * 32 + tx;
    int no = blockIdx.x * 32 + ty;
#pragma unroll
    for (int j = 0; j < 32; j += 8)
        g_B[(size_t)(no + j) * K2H + ko] = __float2half(tile[tx][ty + j]);
}

// ============================================================
// K1: scores + base logits
// ============================================================
__global__ __launch_bounds__(256) void k1_scores_base(
    const float* __restrict__ x, const float* __restrict__ Wc,
    const float* __restrict__ bc, const float* __restrict__ wa,
    const float* __restrict__ ba)
{
    const int row = blockIdx.x;
    const int tid = threadIdx.x;
    const int lane = tid & 31, warp = tid >> 5;
    const float* xr = x + (size_t)row * H;

    float vals[10];
#pragma unroll
    for (int r = 0; r < 10; r++) vals[r] = 0.f;

    for (int h = tid; h < H; h += 256) {
        float xv = xr[h];
        vals[0] += xv * wa[h];
        const float* wcr = Wc + h * L;
#pragma unroll
        for (int l = 0; l < L; l++) vals[1 + l] += xv * wcr[l];
    }
    __shared__ float red[8][10];
#pragma unroll
    for (int r = 0; r < 10; r++) {
        float v = vals[r];
#pragma unroll
        for (int o = 16; o > 0; o >>= 1) v += __shfl_down_sync(0xffffffffu, v, o);
        if (lane == 0) red[warp][r] = v;
    }
    __syncthreads();
    if (tid < 10) {
        float t = 0.f;
#pragma unroll
        for (int w = 0; w < 8; w++) t += red[w][tid];
        if (tid == 0) g_scores[row] = t + ba[0];
        else g_base[row * L + (tid - 1)] = t + bc[tid - 1];
    }
}

// ============================================================
// K2: window softmax + weighted context; emit [x|ctx] fp16
// ============================================================
__global__ __launch_bounds__(256) void k2_ctx(const float* __restrict__ x)
{
    const int row = blockIdx.x;
    const int b = row / SEQ;
    const int s = row % SEQ;
    const int tid = threadIdx.x;

    __shared__ float attn_s[W_WIN];
    if (tid < 32) {
        int w = tid;
        int idx = s + (w - M_WIN);
        bool valid = (w < W_WIN) && (idx >= 0) && (idx < SEQ);
        float sc = valid ? g_scores[b * SEQ + idx] : -INFINITY;
        float m = sc;
#pragma unroll
        for (int o = 16; o > 0; o >>= 1) m = fmaxf(m, __shfl_xor_sync(0xffffffffu, m, o));
        float e = valid ? expf(sc - m) : 0.f;
        float sum = e;
#pragma unroll
        for (int o = 16; o > 0; o >>= 1) sum += __shfl_xor_sync(0xffffffffu, sum, o);
        if (w < W_WIN) attn_s[w] = e / sum;
    }
    __syncthreads();

    float a[W_WIN];
    const float* rows[W_WIN];
#pragma unroll
    for (int w = 0; w < W_WIN; w++) {
        a[w] = attn_s[w];
        int idx = s + (w - M_WIN);
        idx = max(0, min(SEQ - 1, idx));
        rows[w] = x + ((size_t)(b * SEQ + idx)) * H;
    }

    __half* arow = g_A + (size_t)row * K2H;
    for (int h = tid; h < H; h += 256) {
        float acc = 0.f;
#pragma unroll
        for (int w = 0; w < W_WIN; w++) acc += a[w] * rows[w][h];
        arow[h] = __float2half(rows[M_WIN][h]);
        arow[H + h] = __float2half(acc);
    }
}

// ============================================================
// K3: single-pass fp16 HMMA GEMM: g_h = [x|ctx] @ W1 + b1
// BM=128 BN=128 BK=128(halfs), 3-stage cp.async single-sync pipeline,
// SW128 smem (256B logical rows), 512 thr (16 warps 4Mx4N, tile 32x32)
// ============================================================
#define BM3 128
#define BN3 128
#define BK3 128
#define NIT (K2H / BK3)            // 12
#define NSTG 3
#define SA 0
#define SB (32 * 1024)
#define STAGE_BYTES (64 * 1024)
#define SMEM_TOTAL3 (1024 + NSTG * STAGE_BYTES)

// chunk -> smem byte offset. row = m/n index, ch = 16B-chunk index (0..15)
__device__ __forceinline__ uint32_t k3_off(int row, int ch) {
    int rowIdx = row * 2 + (ch >> 3);
    return rowIdx * 128 + (((ch & 7) ^ (rowIdx & 7)) << 4);
}

__global__ __launch_bounds__(512, 1) void k3_mma(const float* __restrict__ b1)
{
    extern __shared__ char smem_raw[];
    uint32_t sraw = smem_u32(smem_raw);
    const uint32_t sbase = (sraw + 1023u) & ~1023u;

    const int tid = threadIdx.x;
    const int lane = tid & 31, wid = tid >> 5;
    const int warpM = wid & 3;        // 4 M warps
    const int warpN = wid >> 2;       // 4 N warps
    const int m0 = blockIdx.y * BM3;
    const int n0 = blockIdx.x * BN3;

    // ---- gmem load roles: thread t -> row t>>2, chunks (t&3)*4 .. +3 ----
    const int ldRow = tid >> 2;
    const int ldC0 = (tid & 3) * 4;
    const __half* gA = g_A + (size_t)(m0 + ldRow) * K2H + ldC0 * 8;
    const __half* gB = g_B + (size_t)(n0 + ldRow) * K2H + ldC0 * 8;
    uint32_t dOff[4];
#pragma unroll
    for (int i = 0; i < 4; i++) dOff[i] = k3_off(ldRow, ldC0 + i);

    // ---- ldmatrix address prep ----
    int aRow[2];
    aRow[0] = warpM * 32 + (lane & 15);
    aRow[1] = aRow[0] + 16;
    const int aCB = lane >> 4;
    int bRow[2];
#pragma unroll
    for (int p = 0; p < 2; p++)
        bRow[p] = warpN * 32 + p * 16 + (lane & 7) + ((lane >> 4) << 3);
    const int bCB = (lane >> 3) & 1;

    float c[2][4][4];
#pragma unroll
    for (int f = 0; f < 2; f++)
#pragma unroll
        for (int j = 0; j < 4; j++)
#pragma unroll
            for (int q = 0; q < 4; q++) c[f][j][q] = 0.f;

    // ---- prologue: stages 0..NSTG-2 ----
#pragma unroll
    for (int st = 0; st < NSTG - 1; st++) {
        uint32_t sd = sbase + st * STAGE_BYTES;
        const int kb = st * BK3;
#pragma unroll
        for (int i = 0; i < 4; i++) {
            cp16(sd + SA + dOff[i], gA + kb + i * 8);
            cp16(sd + SB + dOff[i], gB + kb + i * 8);
        }
        cp_commit();
    }

    for (int it = 0; it < NIT; ++it) {
        cp_wait<NSTG - 2>();      // stage `it` resident
        __syncthreads();          // all warps done reading stage it-1

        const int pf = it + NSTG - 1;
        if (pf < NIT) {
            const uint32_t sn = sbase + (pf % NSTG) * STAGE_BYTES;
            const int kb = pf * BK3;
#pragma unroll
            for (int i = 0; i < 4; i++) {
                cp16(sn + SA + dOff[i], gA + kb + i * 8);
                cp16(sn + SB + dOff[i], gB + kb + i * 8);
            }
        }
        cp_commit();

        const uint32_t sd = sbase + (it % NSTG) * STAGE_BYTES;
#pragma unroll
        for (int s = 0; s < 8; s++) {          // 8 k16-steps per BK=128
            uint32_t af[2][4], bf[2][4];
#pragma unroll
            for (int f = 0; f < 2; f++)
                ldsm_x4(af[f], sd + SA + k3_off(aRow[f], 2 * s + aCB));
#pragma unroll
            for (int p = 0; p < 2; p++)
                ldsm_x4(bf[p], sd + SB + k3_off(bRow[p], 2 * s + bCB));
#pragma unroll
            for (int p = 0; p < 2; p++)
#pragma unroll
                for (int f = 0; f < 2; f++) {
                    mma_f16(c[f][2 * p],     af[f], bf[p]);
                    mma_f16(c[f][2 * p + 1], af[f], bf[p] + 2);
                }
        }
    }

    // ---- epilogue: +b1 -> g_h ----
    const int mBase = m0 + warpM * 32 + (lane >> 2);
    const int nBase = n0 + warpN * 32 + (lane & 3) * 2;
#pragma unroll
    for (int f = 0; f < 2; f++) {
#pragma unroll
        for (int j = 0; j < 4; j++) {
            int n = nBase + j * 8;
            float b0 = b1[n], b1v = b1[n + 1];
            int m = mBase + f * 16;
            float2 o0 = make_float2(c[f][j][0] + b0, c[f][j][1] + b1v);
            float2 o1 = make_float2(c[f][j][2] + b0, c[f][j][3] + b1v);
            *(float2*)&g_h[(size_t)m * H + n] = o0;
            *(float2*)&g_h[(size_t)(m + 8) * H + n] = o1;
        }
    }
}

// ============================================================
// K4: layernorm + exact gelu + W2 + combine
// 768 threads, 4 rows concurrently (192 thr/row, float4 loads), 16 rows/blk
// ============================================================
#define K4_ROWS 16
__global__ __launch_bounds__(768) void k4_ln_gelu_out(
    const float* __restrict__ gamma, const float* __restrict__ beta,
    const float* __restrict__ W2, const float* __restrict__ b2,
    float* __restrict__ out)
{
    const int tid = threadIdx.x;
    const int lane = tid & 31;
    const int rgrp = tid / 192;       // 0..3 concurrent rows
    const int tIn = tid % 192;        // thread within row
    const int warpIn = tIn >> 5;      // 0..5

    __shared__ float w2s[H * L];      // 27 KB
    __shared__ float gb[2 * H];       // 6 KB
    for (int i = tid; i < H * L; i += 768) w2s[i] = W2[i];
    for (int i = tid; i < H; i += 768) { gb[i] = gamma[i]; gb[H + i] = beta[i]; }

    __shared__ float rbuf[4][6][2];
    __shared__ float red[4][6][L];
    __shared__ float musd[4][2];
    __syncthreads();

#pragma unroll
    for (int pass = 0; pass < K4_ROWS / 4; pass++) {
        const int row = blockIdx.x * K4_ROWS + pass * 4 + rgrp;
        const float4 hv = ((const float4*)(g_h + (size_t)row * H))[tIn];

        float s1 = hv.x + hv.y + hv.z + hv.w;
        float s2 = hv.x * hv.x + hv.y * hv.y + hv.z * hv.z + hv.w * hv.w;
#pragma unroll
        for (int o = 16; o > 0; o >>= 1) {
            s1 += __shfl_down_sync(0xffffffffu, s1, o);
            s2 += __shfl_down_sync(0xffffffffu, s2, o);
        }
        if (lane == 0) { rbuf[rgrp][warpIn][0] = s1; rbuf[rgrp][warpIn][1] = s2; }
        __syncthreads();
        if (tIn == 0) {
            float a = 0.f, bsum = 0.f;
#pragma unroll
            for (int w = 0; w < 6; w++) { a += rbuf[rgrp][w][0]; bsum += rbuf[rgrp][w][1]; }
            float mu = a * (1.0f / H);
            float var = bsum * (1.0f / H) - mu * mu;
            musd[rgrp][0] = mu;
            musd[rgrp][1] = rsqrtf(var + 1e-5f);
        }
        __syncthreads();
        const float mu = musd[rgrp][0];
        const float rstd = musd[rgrp][1];

        float bl[L];
#pragma unroll
        for (int l = 0; l < L; l++) bl[l] = 0.f;
        float he[4] = {hv.x, hv.y, hv.z, hv.w};
#pragma unroll
        for (int e = 0; e < 4; e++) {
            int idx = tIn * 4 + e;
            float xv = (he[e] - mu) * rstd * gb[idx] + gb[H + idx];
            float g = xv * normcdff(xv);
            const float* w2r = &w2s[idx * L];
#pragma unroll
            for (int l = 0; l < L; l++) bl[l] += g * w2r[l];
        }
#pragma unroll
        for (int r = 0; r < L; r++) {
            float val = bl[r];
#pragma unroll
            for (int o = 16; o > 0; o >>= 1) val += __shfl_down_sync(0xffffffffu, val, o);
            if (lane == 0) red[rgrp][warpIn][r] = val;
        }
        __syncthreads();
        if (tIn < L) {
            float t = 0.f;
#pragma unroll
            for (int w = 0; w < 6; w++) t += red[rgrp][w][tIn];
            out[row * L + tIn] = 0.5f * g_base[row * L + tIn] + 0.5f * (t + b2[tIn]);
        }
        __syncthreads();
    }
}

// ============================================================
extern "C" void kernel_launch(void* const* d_in, const int* in_sizes, int n_in,
                              void* d_out, int out_size)
{
    const float* x     = (const float*)d_in[0];
    const float* Wc    = (const float*)d_in[1];
    const float* bc    = (const float*)d_in[2];
    const float* wa    = (const float*)d_in[3];
    const float* ba    = (const float*)d_in[4];
    const float* W1    = (const float*)d_in[5];
    const float* b1    = (const float*)d_in[6];
    const float* gamma = (const float*)d_in[7];
    const float* beta  = (const float*)d_in[8];
    const float* W2    = (const float*)d_in[9];
    const float* b2    = (const float*)d_in[10];
    float* out = (float*)d_out;

    cudaFuncSetAttribute(k3_mma, cudaFuncAttributeMaxDynamicSharedMemorySize, SMEM_TOTAL3);

    kprep_w<<<dim3(H / 32, K2H / 32), dim3(32, 8)>>>(W1);
    k1_scores_base<<<NTOK, 256>>>(x, Wc, bc, wa, ba);
    k2_ctx<<<NTOK, 256>>>(x);
    k3_mma<<<dim3(H / BN3, NTOK / BM3), 512, SMEM_TOTAL3>>>(b1);
    k4_ln_gelu_out<<<NTOK / K4_ROWS, 768>>>(gamma, beta, W2, b2, out);
}

// round 11
// speedup vs baseline: 1.6752x; 1.2180x over previous
#include <cuda_runtime.h>
#include <cuda_fp16.h>
#include <math.h>
#include <cstdint>

#define H 768
#define SEQ 2048
#define BATCH 4
#define NTOK (BATCH * SEQ)   // 8192
#define L 9
#define M_WIN 5
#define W_WIN (2 * M_WIN + 1)  // 11
#define K2H (2 * H)            // 1536

// ---------------- scratch (__device__ globals; no allocs allowed) ----------
__device__ float g_scores[NTOK];
__device__ float g_base[NTOK * L];
__device__ float g_h[NTOK * H];          // 25 MB
__device__ __half g_A[NTOK * K2H];       // 25 MB, fp16 [x|ctx]
__device__ __half g_B[H * K2H];          // W1^T fp16 [N=768][K=1536]

// ---------------- PTX helpers ----------------------------------------------
__device__ __forceinline__ uint32_t smem_u32(const void* p) {
    uint32_t a;
    asm("{ .reg .u64 t; cvta.to.shared.u64 t, %1; cvt.u32.u64 %0, t; }" : "=r"(a) : "l"(p));
    return a;
}
__device__ __forceinline__ void cp16(uint32_t dst, const void* src) {
    asm volatile("cp.async.cg.shared.global [%0], [%1], 16;" :: "r"(dst), "l"(src));
}
__device__ __forceinline__ void cp_commit() {
    asm volatile("cp.async.commit_group;" ::: "memory");
}
template <int N>
__device__ __forceinline__ void cp_wait() {
    asm volatile("cp.async.wait_group %0;" :: "n"(N) : "memory");
}
__device__ __forceinline__ void ldsm_x4(uint32_t* r, uint32_t addr) {
    asm volatile("ldmatrix.sync.aligned.m8n8.x4.shared.b16 {%0,%1,%2,%3}, [%4];"
                 : "=r"(r[0]), "=r"(r[1]), "=r"(r[2]), "=r"(r[3]) : "r"(addr));
}
__device__ __forceinline__ void mma_f16(float* c, const uint32_t* a, const uint32_t* b) {
    asm volatile("mma.sync.aligned.m16n8k16.row.col.f32.f16.f16.f32 "
                 "{%0,%1,%2,%3}, {%4,%5,%6,%7}, {%8,%9}, {%0,%1,%2,%3};"
                 : "+f"(c[0]), "+f"(c[1]), "+f"(c[2]), "+f"(c[3])
                 : "r"(a[0]), "r"(a[1]), "r"(a[2]), "r"(a[3]), "r"(b[0]), "r"(b[1]));
}

// ============================================================
// prep: W1 [K2H][H] fp32 -> W1^T fp16 [H][K2H]
// ============================================================
__global__ __launch_bounds__(256) void kprep_w(const float* __restrict__ W1)
{
    __shared__ float tile[32][33];
    int tx = threadIdx.x, ty = threadIdx.y;           // block (32,8)
    int n = blockIdx.x * 32 + tx;                     // H dim
    int k = blockIdx.y * 32 + ty;                     // K2H dim
#pragma unroll
    for (int j = 0; j < 32; j += 8)
        tile[ty + j][tx] = W1[(size_t)(k + j) * H + n];
    __syncthreads();
    int ko = blockIdx.y * 32 + tx;
    int no = blockIdx.x * 32 + ty;
#pragma unroll
    for (int j = 0; j < 32; j += 8)
        g_B[(size_t)(no + j) * K2H + ko] = __float2half(tile[tx][ty + j]);
}

// ============================================================
// K1: scores + base logits
// ============================================================
__global__ __launch_bounds__(256) void k1_scores_base(
    const float* __restrict__ x, const float* __restrict__ Wc,
    const float* __restrict__ bc, const float* __restrict__ wa,
    const float* __restrict__ ba)
{
    const int row = blockIdx.x;
    const int tid = threadIdx.x;
    const int lane = tid & 31, warp = tid >> 5;
    const float* xr = x + (size_t)row * H;

    float vals[10];
#pragma unroll
    for (int r = 0; r < 10; r++) vals[r] = 0.f;

    for (int h = tid; h < H; h += 256) {
        float xv = xr[h];
        vals[0] += xv * wa[h];
        const float* wcr = Wc + h * L;
#pragma unroll
        for (int l = 0; l < L; l++) vals[1 + l] += xv * wcr[l];
    }
    __shared__ float red[8][10];
#pragma unroll
    for (int r = 0; r < 10; r++) {
        float v = vals[r];
#pragma unroll
        for (int o = 16; o > 0; o >>= 1) v += __shfl_down_sync(0xffffffffu, v, o);
        if (lane == 0) red[warp][r] = v;
    }
    __syncthreads();
    if (tid < 10) {
        float t = 0.f;
#pragma unroll
        for (int w = 0; w < 8; w++) t += red[w][tid];
        if (tid == 0) g_scores[row] = t + ba[0];
        else g_base[row * L + (tid - 1)] = t + bc[tid - 1];
    }
}

// ============================================================
// K2: window softmax + weighted context; emit [x|ctx] fp16
// ============================================================
__global__ __launch_bounds__(256) void k2_ctx(const float* __restrict__ x)
{
    const int row = blockIdx.x;
    const int b = row / SEQ;
    const int s = row % SEQ;
    const int tid = threadIdx.x;

    __shared__ float attn_s[W_WIN];
    if (tid < 32) {
        int w = tid;
        int idx = s + (w - M_WIN);
        bool valid = (w < W_WIN) && (idx >= 0) && (idx < SEQ);
        float sc = valid ? g_scores[b * SEQ + idx] : -INFINITY;
        float m = sc;
#pragma unroll
        for (int o = 16; o > 0; o >>= 1) m = fmaxf(m, __shfl_xor_sync(0xffffffffu, m, o));
        float e = valid ? expf(sc - m) : 0.f;
        float sum = e;
#pragma unroll
        for (int o = 16; o > 0; o >>= 1) sum += __shfl_xor_sync(0xffffffffu, sum, o);
        if (w < W_WIN) attn_s[w] = e / sum;
    }
    __syncthreads();

    float a[W_WIN];
    const float* rows[W_WIN];
#pragma unroll
    for (int w = 0; w < W_WIN; w++) {
        a[w] = attn_s[w];
        int idx = s + (w - M_WIN);
        idx = max(0, min(SEQ - 1, idx));
        rows[w] = x + ((size_t)(b * SEQ + idx)) * H;
    }

    __half* arow = g_A + (size_t)row * K2H;
    for (int h = tid; h < H; h += 256) {
        float acc = 0.f;
#pragma unroll
        for (int w = 0; w < W_WIN; w++) acc += a[w] * rows[w][h];
        arow[h] = __float2half(rows[M_WIN][h]);
        arow[H + h] = __float2half(acc);
    }
}

// ============================================================
// K3: single-pass fp16 HMMA GEMM: g_h = [x|ctx] @ W1 + b1
// BM=128 BN=128 BK=64(halfs = 128B rows), 3-stage cp.async
// single-sync pipeline, 256 thr (8 warps: 4M x 2N, tile 32x64),
// 2 CTAs/SM (97 KB smem each)
// ============================================================
#define BM3 128
#define BN3 128
#define BK3 64
#define NIT (K2H / BK3)            // 24
#define NSTG 3
#define SA 0
#define SB (16 * 1024)
#define STAGE_BYTES (32 * 1024)
#define SMEM_TOTAL3 (1024 + NSTG * STAGE_BYTES)

__global__ __launch_bounds__(256, 2) void k3_mma(const float* __restrict__ b1)
{
    extern __shared__ char smem_raw[];
    uint32_t sraw = smem_u32(smem_raw);
    const uint32_t sbase = (sraw + 1023u) & ~1023u;

    const int tid = threadIdx.x;
    const int lane = tid & 31, wid = tid >> 5;
    const int warpM = wid & 3;        // 4 M warps
    const int warpN = wid >> 2;       // 2 N warps
    const int m0 = blockIdx.y * BM3;
    const int n0 = blockIdx.x * BN3;

    // ---- gmem load roles: thread t -> row t>>1, chunks (t&1)*4 .. +3 ----
    const int ldRow = tid >> 1;
    const int ldC0 = (tid & 1) * 4;
    const __half* gA = g_A + (size_t)(m0 + ldRow) * K2H + ldC0 * 8;
    const __half* gB = g_B + (size_t)(n0 + ldRow) * K2H + ldC0 * 8;
    uint32_t dOff[4];
#pragma unroll
    for (int i = 0; i < 4; i++) {
        int c = ldC0 + i;
        dOff[i] = ldRow * 128 + ((c ^ (ldRow & 7)) << 4);
    }

    // ---- ldmatrix address prep ----
    int aRow[2], aX[2];
    aRow[0] = warpM * 32 + (lane & 15);
    aRow[1] = aRow[0] + 16;
    aX[0] = aRow[0] & 7;
    aX[1] = aRow[1] & 7;
    const int aCB = lane >> 4;
    int bRow[4], bX[4];
#pragma unroll
    for (int p = 0; p < 4; p++) {
        bRow[p] = warpN * 64 + p * 16 + (lane & 7) + ((lane >> 4) << 3);
        bX[p] = bRow[p] & 7;
    }
    const int bCB = (lane >> 3) & 1;

    float c[2][8][4];
#pragma unroll
    for (int f = 0; f < 2; f++)
#pragma unroll
        for (int j = 0; j < 8; j++)
#pragma unroll
            for (int q = 0; q < 4; q++) c[f][j][q] = 0.f;

    // ---- prologue: stages 0..NSTG-2 ----
#pragma unroll
    for (int st = 0; st < NSTG - 1; st++) {
        uint32_t sd = sbase + st * STAGE_BYTES;
        const int kb = st * BK3;
#pragma unroll
        for (int i = 0; i < 4; i++) {
            cp16(sd + SA + dOff[i], gA + kb + i * 8);
            cp16(sd + SB + dOff[i], gB + kb + i * 8);
        }
        cp_commit();
    }

    for (int it = 0; it < NIT; ++it) {
        cp_wait<NSTG - 2>();      // stage `it` resident
        __syncthreads();          // all warps done reading stage it-1

        const int pf = it + NSTG - 1;
        if (pf < NIT) {
            const uint32_t sn = sbase + (pf % NSTG) * STAGE_BYTES;
            const int kb = pf * BK3;
#pragma unroll
            for (int i = 0; i < 4; i++) {
                cp16(sn + SA + dOff[i], gA + kb + i * 8);
                cp16(sn + SB + dOff[i], gB + kb + i * 8);
            }
        }
        cp_commit();

        const uint32_t sd = sbase + (it % NSTG) * STAGE_BYTES;
#pragma unroll
        for (int s = 0; s < 4; s++) {          // 4 k16-steps per BK=64
            uint32_t af[2][4], bf[4][4];
#pragma unroll
            for (int f = 0; f < 2; f++) {
                uint32_t off = aRow[f] * 128 + (((2 * s + aCB) ^ aX[f]) << 4);
                ldsm_x4(af[f], sd + SA + off);
            }
#pragma unroll
            for (int p = 0; p < 4; p++) {
                uint32_t off = bRow[p] * 128 + (((2 * s + bCB) ^ bX[p]) << 4);
                ldsm_x4(bf[p], sd + SB + off);
            }
#pragma unroll
            for (int p = 0; p < 4; p++)
#pragma unroll
                for (int f = 0; f < 2; f++) {
                    mma_f16(c[f][2 * p],     af[f], bf[p]);
                    mma_f16(c[f][2 * p + 1], af[f], bf[p] + 2);
                }
        }
    }

    // ---- epilogue: +b1 -> g_h ----
    const int mBase = m0 + warpM * 32 + (lane >> 2);
    const int nBase = n0 + warpN * 64 + (lane & 3) * 2;
#pragma unroll
    for (int f = 0; f < 2; f++) {
#pragma unroll
        for (int j = 0; j < 8; j++) {
            int n = nBase + j * 8;
            float b0 = b1[n], b1v = b1[n + 1];
            int m = mBase + f * 16;
            float2 o0 = make_float2(c[f][j][0] + b0, c[f][j][1] + b1v);
            float2 o1 = make_float2(c[f][j][2] + b0, c[f][j][3] + b1v);
            *(float2*)&g_h[(size_t)m * H + n] = o0;
            *(float2*)&g_h[(size_t)(m + 8) * H + n] = o1;
        }
    }
}

// ============================================================
// K4: layernorm + exact gelu + W2 + combine
// 768 threads, 4 rows concurrently (192 thr/row, float4 loads), 16 rows/blk
// ============================================================
#define K4_ROWS 16
__global__ __launch_bounds__(768) void k4_ln_gelu_out(
    const float* __restrict__ gamma, const float* __restrict__ beta,
    const float* __restrict__ W2, const float* __restrict__ b2,
    float* __restrict__ out)
{
    const int tid = threadIdx.x;
    const int lane = tid & 31;
    const int rgrp = tid / 192;       // 0..3 concurrent rows
    const int tIn = tid % 192;        // thread within row
    const int warpIn = tIn >> 5;      // 0..5

    __shared__ float w2s[H * L];      // 27 KB
    __shared__ float gb[2 * H];       // 6 KB
    for (int i = tid; i < H * L; i += 768) w2s[i] = W2[i];
    for (int i = tid; i < H; i += 768) { gb[i] = gamma[i]; gb[H + i] = beta[i]; }

    __shared__ float rbuf[4][6][2];
    __shared__ float red[4][6][L];
    __shared__ float musd[4][2];
    __syncthreads();

#pragma unroll
    for (int pass = 0; pass < K4_ROWS / 4; pass++) {
        const int row = blockIdx.x * K4_ROWS + pass * 4 + rgrp;
        const float4 hv = ((const float4*)(g_h + (size_t)row * H))[tIn];

        float s1 = hv.x + hv.y + hv.z + hv.w;
        float s2 = hv.x * hv.x + hv.y * hv.y + hv.z * hv.z + hv.w * hv.w;
#pragma unroll
        for (int o = 16; o > 0; o >>= 1) {
            s1 += __shfl_down_sync(0xffffffffu, s1, o);
            s2 += __shfl_down_sync(0xffffffffu, s2, o);
        }
        if (lane == 0) { rbuf[rgrp][warpIn][0] = s1; rbuf[rgrp][warpIn][1] = s2; }
        __syncthreads();
        if (tIn == 0) {
            float a = 0.f, bsum = 0.f;
#pragma unroll
            for (int w = 0; w < 6; w++) { a += rbuf[rgrp][w][0]; bsum += rbuf[rgrp][w][1]; }
            float mu = a * (1.0f / H);
            float var = bsum * (1.0f / H) - mu * mu;
            musd[rgrp][0] = mu;
            musd[rgrp][1] = rsqrtf(var + 1e-5f);
        }
        __syncthreads();
        const float mu = musd[rgrp][0];
        const float rstd = musd[rgrp][1];

        float bl[L];
#pragma unroll
        for (int l = 0; l < L; l++) bl[l] = 0.f;
        float he[4] = {hv.x, hv.y, hv.z, hv.w};
#pragma unroll
        for (int e = 0; e < 4; e++) {
            int idx = tIn * 4 + e;
            float xv = (he[e] - mu) * rstd * gb[idx] + gb[H + idx];
            float g = xv * normcdff(xv);
            const float* w2r = &w2s[idx * L];
#pragma unroll
            for (int l = 0; l < L; l++) bl[l] += g * w2r[l];
        }
#pragma unroll
        for (int r = 0; r < L; r++) {
            float val = bl[r];
#pragma unroll
            for (int o = 16; o > 0; o >>= 1) val += __shfl_down_sync(0xffffffffu, val, o);
            if (lane == 0) red[rgrp][warpIn][r] = val;
        }
        __syncthreads();
        if (tIn < L) {
            float t = 0.f;
#pragma unroll
            for (int w = 0; w < 6; w++) t += red[rgrp][w][tIn];
            out[row * L + tIn] = 0.5f * g_base[row * L + tIn] + 0.5f * (t + b2[tIn]);
        }
        __syncthreads();
    }
}

// ============================================================
extern "C" void kernel_launch(void* const* d_in, const int* in_sizes, int n_in,
                              void* d_out, int out_size)
{
    const float* x     = (const float*)d_in[0];
    const float* Wc    = (const float*)d_in[1];
    const float* bc    = (const float*)d_in[2];
    const float* wa    = (const float*)d_in[3];
    const float* ba    = (const float*)d_in[4];
    const float* W1    = (const float*)d_in[5];
    const float* b1    = (const float*)d_in[6];
    const float* gamma = (const float*)d_in[7];
    const float* beta  = (const float*)d_in[8];
    const float* W2    = (const float*)d_in[9];
    const float* b2    = (const float*)d_in[10];
    float* out = (float*)d_out;

    cudaFuncSetAttribute(k3_mma, cudaFuncAttributeMaxDynamicSharedMemorySize, SMEM_TOTAL3);

    kprep_w<<<dim3(H / 32, K2H / 32), dim3(32, 8)>>>(W1);
    k1_scores_base<<<NTOK, 256>>>(x, Wc, bc, wa, ba);
    k2_ctx<<<NTOK, 256>>>(x);
    k3_mma<<<dim3(H / BN3, NTOK / BM3), 256, SMEM_TOTAL3>>>(b1);
    k4_ln_gelu_out<<<NTOK / K4_ROWS, 768>>>(gamma, beta, W2, b2, out);
}

// round 12
// speedup vs baseline: 2.0225x; 1.2074x over previous
#include <cuda_runtime.h>
#include <cuda_fp16.h>
#include <math.h>
#include <cstdint>

#define H 768
#define SEQ 2048
#define BATCH 4
#define NTOK (BATCH * SEQ)   // 8192
#define L 9
#define M_WIN 5
#define W_WIN (2 * M_WIN + 1)  // 11
#define K2H (2 * H)            // 1536
#define TOK12 16               // tokens per k12 block
#define NW12 (TOK12 + 2 * M_WIN)  // 26 halo scores

// ---------------- scratch (__device__ globals; no allocs allowed) ----------
__device__ float g_base[NTOK * L];
__device__ float g_h[NTOK * H];          // 25 MB
__device__ __half g_A[NTOK * K2H];       // 25 MB, fp16 [x|ctx]
__device__ __half g_B[H * K2H];          // W1^T fp16 [N=768][K=1536]

// ---------------- PTX helpers ----------------------------------------------
__device__ __forceinline__ uint32_t smem_u32(const void* p) {
    uint32_t a;
    asm("{ .reg .u64 t; cvta.to.shared.u64 t, %1; cvt.u32.u64 %0, t; }" : "=r"(a) : "l"(p));
    return a;
}
__device__ __forceinline__ void cp16(uint32_t dst, const void* src) {
    asm volatile("cp.async.cg.shared.global [%0], [%1], 16;" :: "r"(dst), "l"(src));
}
__device__ __forceinline__ void cp_commit() {
    asm volatile("cp.async.commit_group;" ::: "memory");
}
template <int N>
__device__ __forceinline__ void cp_wait() {
    asm volatile("cp.async.wait_group %0;" :: "n"(N) : "memory");
}
__device__ __forceinline__ void ldsm_x4(uint32_t* r, uint32_t addr) {
    asm volatile("ldmatrix.sync.aligned.m8n8.x4.shared.b16 {%0,%1,%2,%3}, [%4];"
                 : "=r"(r[0]), "=r"(r[1]), "=r"(r[2]), "=r"(r[3]) : "r"(addr));
}
__device__ __forceinline__ void mma_f16(float* c, const uint32_t* a, const uint32_t* b) {
    asm volatile("mma.sync.aligned.m16n8k16.row.col.f32.f16.f16.f32 "
                 "{%0,%1,%2,%3}, {%4,%5,%6,%7}, {%8,%9}, {%0,%1,%2,%3};"
                 : "+f"(c[0]), "+f"(c[1]), "+f"(c[2]), "+f"(c[3])
                 : "r"(a[0]), "r"(a[1]), "r"(a[2]), "r"(a[3]), "r"(b[0]), "r"(b[1]));
}

// ============================================================
// prep: W1 [K2H][H] fp32 -> W1^T fp16 [H][K2H]
// ============================================================
__global__ __launch_bounds__(256) void kprep_w(const float* __restrict__ W1)
{
    __shared__ float tile[32][33];
    int tx = threadIdx.x, ty = threadIdx.y;           // block (32,8)
    int n = blockIdx.x * 32 + tx;                     // H dim
    int k = blockIdx.y * 32 + ty;                     // K2H dim
#pragma unroll
    for (int j = 0; j < 32; j += 8)
        tile[ty + j][tx] = W1[(size_t)(k + j) * H + n];
    __syncthreads();
    int ko = blockIdx.y * 32 + tx;
    int no = blockIdx.x * 32 + ty;
#pragma unroll
    for (int j = 0; j < 32; j += 8)
        g_B[(size_t)(no + j) * K2H + ko] = __float2half(tile[tx][ty + j]);
}

// ============================================================
// K12: fused scores + base logits + window softmax + context
//      16 tokens per block, 256 threads
// ============================================================
__global__ __launch_bounds__(256) void k12_fused(
    const float* __restrict__ x, const float* __restrict__ wa,
    const float* __restrict__ Wc, const float* __restrict__ bc)
{
    const int row0 = blockIdx.x * TOK12;
    const int b = row0 / SEQ;
    const int s0 = row0 % SEQ;
    const int tid = threadIdx.x;
    const int lane = tid & 31, warp = tid >> 5;
    const float* bbase = x + (size_t)b * SEQ * H;

    __shared__ float scbuf[NW12];
    __shared__ float attn[TOK12][W_WIN + 1];

    // ---- phase 1a: 26 halo scores (ba omitted: softmax shift-invariant) ----
    for (int j = warp; j < NW12; j += 8) {
        int sseq = s0 - M_WIN + j;
        int sc = min(max(sseq, 0), SEQ - 1);
        const float* xr = bbase + (size_t)sc * H;
        float d = 0.f;
#pragma unroll
        for (int k = 0; k < 12; k++) {
            int h2 = 2 * lane + 64 * k;
            float2 v = *(const float2*)&xr[h2];
            float2 w2 = *(const float2*)&wa[h2];
            d += v.x * w2.x + v.y * w2.y;
        }
#pragma unroll
        for (int o = 16; o > 0; o >>= 1) d += __shfl_down_sync(0xffffffffu, d, o);
        if (lane == 0) scbuf[j] = d;
    }

    // ---- phase 1b: base logits for own 2 tokens per warp ----
#pragma unroll
    for (int tt = 0; tt < 2; tt++) {
        const int t = warp * 2 + tt;
        const float* xr = bbase + (size_t)(s0 + t) * H;
        float acc[L];
#pragma unroll
        for (int l = 0; l < L; l++) acc[l] = 0.f;
#pragma unroll
        for (int k = 0; k < 12; k++) {
            int h2 = 2 * lane + 64 * k;
            float2 v = *(const float2*)&xr[h2];
            const float* w0 = &Wc[(size_t)h2 * L];
#pragma unroll
            for (int l = 0; l < L; l++) acc[l] += v.x * w0[l] + v.y * w0[l + L];
        }
#pragma unroll
        for (int l = 0; l < L; l++) {
#pragma unroll
            for (int o = 16; o > 0; o >>= 1)
                acc[l] += __shfl_down_sync(0xffffffffu, acc[l], o);
        }
        if (lane == 0) {
#pragma unroll
            for (int l = 0; l < L; l++)
                g_base[(row0 + t) * L + l] = acc[l] + bc[l];
        }
    }
    __syncthreads();

    // ---- phase 2: per-token softmax (one lane per token) ----
    if (tid < TOK12) {
        const int i = tid;
        const int sseq = s0 + i;
        float e[W_WIN];
        float m = -INFINITY;
#pragma unroll
        for (int w = 0; w < W_WIN; w++) {
            int idx = sseq - M_WIN + w;
            bool v = (idx >= 0) && (idx < SEQ);
            float scv = v ? scbuf[i + w] : -INFINITY;
            e[w] = scv;
            m = fmaxf(m, scv);
        }
        float sum = 0.f;
#pragma unroll
        for (int w = 0; w < W_WIN; w++) {
            int idx = sseq - M_WIN + w;
            bool v = (idx >= 0) && (idx < SEQ);
            float ev = v ? expf(e[w] - m) : 0.f;
            e[w] = ev;
            sum += ev;
        }
        float inv = 1.f / sum;
#pragma unroll
        for (int w = 0; w < W_WIN; w++) attn[i][w] = e[w] * inv;
    }
    __syncthreads();

    // ---- phase 3: weighted context + emit [x|ctx] fp16 ----
#pragma unroll
    for (int tt = 0; tt < 2; tt++) {
        const int t = warp * 2 + tt;
        const int sseq = s0 + t;
        const float* rp[W_WIN];
        float aw[W_WIN];
#pragma unroll
        for (int w = 0; w < W_WIN; w++) {
            int idx = min(max(sseq - M_WIN + w, 0), SEQ - 1);
            rp[w] = bbase + (size_t)idx * H;
            aw[w] = attn[t][w];
        }
        __half* arow = g_A + (size_t)(row0 + t) * K2H;
#pragma unroll
        for (int k = 0; k < 12; k++) {
            int h2 = 2 * lane + 64 * k;
            float2 xc = *(const float2*)&rp[M_WIN][h2];
            float ax = 0.f, ay = 0.f;
#pragma unroll
            for (int w = 0; w < W_WIN; w++) {
                float2 v = *(const float2*)&rp[w][h2];
                ax += aw[w] * v.x;
                ay += aw[w] * v.y;
            }
            *(__half2*)&arow[h2] = __floats2half2_rn(xc.x, xc.y);
            *(__half2*)&arow[H + h2] = __floats2half2_rn(ax, ay);
        }
    }
}

// ============================================================
// K3: single-pass fp16 HMMA GEMM: g_h = [x|ctx] @ W1 + b1
// BM=128 BN=128 BK=64(halfs = 128B rows), 3-stage cp.async
// single-sync pipeline, 256 thr (8 warps: 4M x 2N, tile 32x64),
// 2 CTAs/SM (97 KB smem each)
// ============================================================
#define BM3 128
#define BN3 128
#define BK3 64
#define NIT (K2H / BK3)            // 24
#define NSTG 3
#define SA 0
#define SB (16 * 1024)
#define STAGE_BYTES (32 * 1024)
#define SMEM_TOTAL3 (1024 + NSTG * STAGE_BYTES)

__global__ __launch_bounds__(256, 2) void k3_mma(const float* __restrict__ b1)
{
    extern __shared__ char smem_raw[];
    uint32_t sraw = smem_u32(smem_raw);
    const uint32_t sbase = (sraw + 1023u) & ~1023u;

    const int tid = threadIdx.x;
    const int lane = tid & 31, wid = tid >> 5;
    const int warpM = wid & 3;        // 4 M warps
    const int warpN = wid >> 2;       // 2 N warps
    const int m0 = blockIdx.y * BM3;
    const int n0 = blockIdx.x * BN3;

    // ---- gmem load roles: thread t -> row t>>1, chunks (t&1)*4 .. +3 ----
    const int ldRow = tid >> 1;
    const int ldC0 = (tid & 1) * 4;
    const __half* gA = g_A + (size_t)(m0 + ldRow) * K2H + ldC0 * 8;
    const __half* gB = g_B + (size_t)(n0 + ldRow) * K2H + ldC0 * 8;
    uint32_t dOff[4];
#pragma unroll
    for (int i = 0; i < 4; i++) {
        int c = ldC0 + i;
        dOff[i] = ldRow * 128 + ((c ^ (ldRow & 7)) << 4);
    }

    // ---- ldmatrix address prep ----
    int aRow[2], aX[2];
    aRow[0] = warpM * 32 + (lane & 15);
    aRow[1] = aRow[0] + 16;
    aX[0] = aRow[0] & 7;
    aX[1] = aRow[1] & 7;
    const int aCB = lane >> 4;
    int bRow[4], bX[4];
#pragma unroll
    for (int p = 0; p < 4; p++) {
        bRow[p] = warpN * 64 + p * 16 + (lane & 7) + ((lane >> 4) << 3);
        bX[p] = bRow[p] & 7;
    }
    const int bCB = (lane >> 3) & 1;

    float c[2][8][4];
#pragma unroll
    for (int f = 0; f < 2; f++)
#pragma unroll
        for (int j = 0; j < 8; j++)
#pragma unroll
            for (int q = 0; q < 4; q++) c[f][j][q] = 0.f;

    // ---- prologue: stages 0..NSTG-2 ----
#pragma unroll
    for (int st = 0; st < NSTG - 1; st++) {
        uint32_t sd = sbase + st * STAGE_BYTES;
        const int kb = st * BK3;
#pragma unroll
        for (int i = 0; i < 4; i++) {
            cp16(sd + SA + dOff[i], gA + kb + i * 8);
            cp16(sd + SB + dOff[i], gB + kb + i * 8);
        }
        cp_commit();
    }

    for (int it = 0; it < NIT; ++it) {
        cp_wait<NSTG - 2>();      // stage `it` resident
        __syncthreads();          // all warps done reading stage it-1

        const int pf = it + NSTG - 1;
        if (pf < NIT) {
            const uint32_t sn = sbase + (pf % NSTG) * STAGE_BYTES;
            const int kb = pf * BK3;
#pragma unroll
            for (int i = 0; i < 4; i++) {
                cp16(sn + SA + dOff[i], gA + kb + i * 8);
                cp16(sn + SB + dOff[i], gB + kb + i * 8);
            }
        }
        cp_commit();

        const uint32_t sd = sbase + (it % NSTG) * STAGE_BYTES;
#pragma unroll
        for (int s = 0; s < 4; s++) {          // 4 k16-steps per BK=64
            uint32_t af[2][4], bf[4][4];
#pragma unroll
            for (int f = 0; f < 2; f++) {
                uint32_t off = aRow[f] * 128 + (((2 * s + aCB) ^ aX[f]) << 4);
                ldsm_x4(af[f], sd + SA + off);
            }
#pragma unroll
            for (int p = 0; p < 4; p++) {
                uint32_t off = bRow[p] * 128 + (((2 * s + bCB) ^ bX[p]) << 4);
                ldsm_x4(bf[p], sd + SB + off);
            }
#pragma unroll
            for (int p = 0; p < 4; p++)
#pragma unroll
                for (int f = 0; f < 2; f++) {
                    mma_f16(c[f][2 * p],     af[f], bf[p]);
                    mma_f16(c[f][2 * p + 1], af[f], bf[p] + 2);
                }
        }
    }

    // ---- epilogue: +b1 -> g_h ----
    const int mBase = m0 + warpM * 32 + (lane >> 2);
    const int nBase = n0 + warpN * 64 + (lane & 3) * 2;
#pragma unroll
    for (int f = 0; f < 2; f++) {
#pragma unroll
        for (int j = 0; j < 8; j++) {
            int n = nBase + j * 8;
            float b0 = b1[n], b1v = b1[n + 1];
            int m = mBase + f * 16;
            float2 o0 = make_float2(c[f][j][0] + b0, c[f][j][1] + b1v);
            float2 o1 = make_float2(c[f][j][2] + b0, c[f][j][3] + b1v);
            *(float2*)&g_h[(size_t)m * H + n] = o0;
            *(float2*)&g_h[(size_t)(m + 8) * H + n] = o1;
        }
    }
}

// ============================================================
// K4: layernorm + exact gelu + W2 + combine
// 768 threads, 4 rows concurrently (192 thr/row, float4 loads), 16 rows/blk
// ============================================================
#define K4_ROWS 16
__global__ __launch_bounds__(768) void k4_ln_gelu_out(
    const float* __restrict__ gamma, const float* __restrict__ beta,
    const float* __restrict__ W2, const float* __restrict__ b2,
    float* __restrict__ out)
{
    const int tid = threadIdx.x;
    const int lane = tid & 31;
    const int rgrp = tid / 192;       // 0..3 concurrent rows
    const int tIn = tid % 192;        // thread within row
    const int warpIn = tIn >> 5;      // 0..5

    __shared__ float w2s[H * L];      // 27 KB
    __shared__ float gb[2 * H];       // 6 KB
    for (int i = tid; i < H * L; i += 768) w2s[i] = W2[i];
    for (int i = tid; i < H; i += 768) { gb[i] = gamma[i]; gb[H + i] = beta[i]; }

    __shared__ float rbuf[4][6][2];
    __shared__ float red[4][6][L];
    __shared__ float musd[4][2];
    __syncthreads();

#pragma unroll
    for (int pass = 0; pass < K4_ROWS / 4; pass++) {
        const int row = blockIdx.x * K4_ROWS + pass * 4 + rgrp;
        const float4 hv = ((const float4*)(g_h + (size_t)row * H))[tIn];

        float s1 = hv.x + hv.y + hv.z + hv.w;
        float s2 = hv.x * hv.x + hv.y * hv.y + hv.z * hv.z + hv.w * hv.w;
#pragma unroll
        for (int o = 16; o > 0; o >>= 1) {
            s1 += __shfl_down_sync(0xffffffffu, s1, o);
            s2 += __shfl_down_sync(0xffffffffu, s2, o);
        }
        if (lane == 0) { rbuf[rgrp][warpIn][0] = s1; rbuf[rgrp][warpIn][1] = s2; }
        __syncthreads();
        if (tIn == 0) {
            float a = 0.f, bsum = 0.f;
#pragma unroll
            for (int w = 0; w < 6; w++) { a += rbuf[rgrp][w][0]; bsum += rbuf[rgrp][w][1]; }
            float mu = a * (1.0f / H);
            float var = bsum * (1.0f / H) - mu * mu;
            musd[rgrp][0] = mu;
            musd[rgrp][1] = rsqrtf(var + 1e-5f);
        }
        __syncthreads();
        const float mu = musd[rgrp][0];
        const float rstd = musd[rgrp][1];

        float bl[L];
#pragma unroll
        for (int l = 0; l < L; l++) bl[l] = 0.f;
        float he[4] = {hv.x, hv.y, hv.z, hv.w};
#pragma unroll
        for (int e = 0; e < 4; e++) {
            int idx = tIn * 4 + e;
            float xv = (he[e] - mu) * rstd * gb[idx] + gb[H + idx];
            float g = xv * normcdff(xv);
            const float* w2r = &w2s[idx * L];
#pragma unroll
            for (int l = 0; l < L; l++) bl[l] += g * w2r[l];
        }
#pragma unroll
        for (int r = 0; r < L; r++) {
            float val = bl[r];
#pragma unroll
            for (int o = 16; o > 0; o >>= 1) val += __shfl_down_sync(0xffffffffu, val, o);
            if (lane == 0) red[rgrp][warpIn][r] = val;
        }
        __syncthreads();
        if (tIn < L) {
            float t = 0.f;
#pragma unroll
            for (int w = 0; w < 6; w++) t += red[rgrp][w][tIn];
            out[row * L + tIn] = 0.5f * g_base[row * L + tIn] + 0.5f * (t + b2[tIn]);
        }
        __syncthreads();
    }
}

// ============================================================
extern "C" void kernel_launch(void* const* d_in, const int* in_sizes, int n_in,
                              void* d_out, int out_size)
{
    const float* x     = (const float*)d_in[0];
    const float* Wc    = (const float*)d_in[1];
    const float* bc    = (const float*)d_in[2];
    const float* wa    = (const float*)d_in[3];
    const float* W1    = (const float*)d_in[5];
    const float* b1    = (const float*)d_in[6];
    const float* gamma = (const float*)d_in[7];
    const float* beta  = (const float*)d_in[8];
    const float* W2    = (const float*)d_in[9];
    const float* b2    = (const float*)d_in[10];
    float* out = (float*)d_out;

    cudaFuncSetAttribute(k3_mma, cudaFuncAttributeMaxDynamicSharedMemorySize, SMEM_TOTAL3);

    kprep_w<<<dim3(H / 32, K2H / 32), dim3(32, 8)>>>(W1);
    k12_fused<<<NTOK / TOK12, 256>>>(x, wa, Wc, bc);
    k3_mma<<<dim3(H / BN3, NTOK / BM3), 256, SMEM_TOTAL3>>>(b1);
    k4_ln_gelu_out<<<NTOK / K4_ROWS, 768>>>(gamma, beta, W2, b2, out);
}